// round 16
// baseline (speedup 1.0000x reference)
#include <cuda_runtime.h>
#include <cstdint>

// VectorQuantizer: input (16, 64, 8192) fp32, codebook (1024, 64) fp32
// score(n,k) = 0.5*||e_k||^2 - x_n . e_k   (argmin-equivalent to ||x - e||^2)
//
// R16: two-kernel, codebook-half-resident design.
//  A: CTA = 256 tokens x 512 codes (132KB E image resident in smem, filled by
//     a pipelined 8-group cp.async sequence). After fill: ZERO barriers/waits.
//     Inner loop = R8's verified 8x8 fp32x2 register tile + mono-key argmin.
//     Emits per-(token, half) best key (mono score || global idx) to scratch.
//  B: key = min(half0, half1)  -> gather + coalesced scatter + idx.

#define Dd 64
#define Kk 1024
#define Bb 16
#define Tt 8192
#define Nn (Bb * Tt)             // 131072 tokens
#define TPB 256
#define TOK 256                  // tokens per CTA
#define NSEG 8                   // 64-code segments per half

#define GSTRIDE 2064             // 8-entry group: 32 dpairs*64B + 16B pad
#define SEG_BYTES (8 * GSTRIDE)          // 16512 (64 codes)
#define HALF_BYTES (NSEG * SEG_BYTES)    // 132096 (512 codes)
#define XOFF 0                   // X image: 32 groups
#define XBYTES (32 * GSTRIDE)            // 66048
#define EOFF XBYTES
#define HOFF (EOFF + HALF_BYTES)         // 198144 (+2KB norms)
#define SMEM_BYTES (HOFF + 2048)         // 200192

__device__ float g_half[Kk];
__device__ __align__(16) unsigned char g_cbT[Kk / 64 * SEG_BYTES];  // 16 chunks of 64 codes
__device__ unsigned long long g_keys[2 * Nn];                       // scratch: per (half, token)

typedef unsigned long long u64;

// ---- packed f32x2 helpers ----
__device__ __forceinline__ u64 pk2(float a, float b) {
    u64 r; asm("mov.b64 %0, {%1, %2};" : "=l"(r) : "f"(a), "f"(b)); return r;
}
__device__ __forceinline__ void fma2(u64& acc, u64 a, u64 b) {
    asm("fma.rn.f32x2 %0, %1, %2, %0;" : "+l"(acc) : "l"(a), "l"(b));
}
__device__ __forceinline__ float hsum2(u64 v) {
    float lo, hi; asm("mov.b64 {%0, %1}, %2;" : "=f"(lo), "=f"(hi) : "l"(v));
    return lo + hi;
}
// order-preserving float -> u32 (exact, bijective)
__device__ __forceinline__ uint32_t mono(float f) {
    uint32_t b = __float_as_uint(f);
    return b ^ (uint32_t)(((int32_t)b >> 31) | 0x80000000);
}

// ---- cp.async helpers ----
__device__ __forceinline__ void cp16(uint32_t dst, const void* src) {
    uint64_t g = __cvta_generic_to_global(src);
    asm volatile("cp.async.cg.shared.global [%0], [%1], 16;" :: "r"(dst), "l"(g) : "memory");
}
__device__ __forceinline__ void cp_commit() { asm volatile("cp.async.commit_group;" ::: "memory"); }
__device__ __forceinline__ void cp_waitn(int n) {
    // runtime-bounded wait: n is small compile-time-unrolled below
    switch (n) {
        case 0: asm volatile("cp.async.wait_group 0;" ::: "memory"); break;
        case 1: asm volatile("cp.async.wait_group 1;" ::: "memory"); break;
        case 2: asm volatile("cp.async.wait_group 2;" ::: "memory"); break;
        case 3: asm volatile("cp.async.wait_group 3;" ::: "memory"); break;
        case 4: asm volatile("cp.async.wait_group 4;" ::: "memory"); break;
        case 5: asm volatile("cp.async.wait_group 5;" ::: "memory"); break;
        case 6: asm volatile("cp.async.wait_group 6;" ::: "memory"); break;
        default: asm volatile("cp.async.wait_group 7;" ::: "memory"); break;
    }
}
__device__ __forceinline__ uint32_t s2u(const void* p) {
    uint32_t a;
    asm("{ .reg .u64 t; cvta.to.shared.u64 t, %1; cvt.u32.u64 %0, t; }" : "=r"(a) : "l"(p));
    return a;
}

// ---- prologue: 0.5||e||^2 + padded transposed codebook image (R8-verified) ----
__global__ void vq_pre(const float* __restrict__ cb) {
    int k = blockIdx.x * blockDim.x + threadIdx.x;
    if (k >= Kk) return;
    const float* row = cb + k * Dd;
    float s = 0.f;
    unsigned char* dst = g_cbT + (k >> 6) * SEG_BYTES + ((k >> 3) & 7) * GSTRIDE + (k & 7) * 8;
#pragma unroll
    for (int i = 0; i < 32; i++) {
        float a = row[2 * i], b = row[2 * i + 1];
        s += a * a + b * b;
        *(u64*)(dst + i * 64) = pk2(a, b);
    }
    g_half[k] = 0.5f * s;
}

// ---- kernel A: one tile x one codebook half ----
__global__ __launch_bounds__(TPB, 1)
void vq_half(const float* __restrict__ input) {
    extern __shared__ __align__(16) unsigned char smem[];
    const uint32_t sb = s2u(smem);

    const int tid = threadIdx.x;
    const int kl  = tid & 7;          // code-group lane (8 codes)
    const int ml  = tid >> 3;         // token group (8 tokens), 0..31
    const int tile = blockIdx.x;      // 0..511
    const int half = blockIdx.y;      // 0..1
    const int b    = tile >> 5;       // 32 tiles per batch
    const int tb   = (tile & 31) * TOK;

    // issue the 8-segment E fill first (max overlap with X staging)
    {
        const unsigned char* src = g_cbT + (size_t)half * HALF_BYTES;
#pragma unroll
        for (int s = 0; s < NSEG; s++) {
#pragma unroll
            for (int r = 0; r < 5; r++) {
                int idx = tid + r * TPB;
                if (idx < SEG_BYTES / 16)
                    cp16(sb + EOFF + s * SEG_BYTES + idx * 16, src + (size_t)s * SEG_BYTES + idx * 16);
            }
            cp_commit();
        }
    }

    // stage X tile (token tb + tid), packed pairs along D; coalesced LDG
    {
        const float* inb = input + (size_t)b * Dd * Tt + tb + tid;
        unsigned char* xdst = smem + XOFF + (tid >> 3) * GSTRIDE + (tid & 7) * 8;
#pragma unroll 8
        for (int i = 0; i < 32; i++) {
            float a = inb[(size_t)(2 * i) * Tt];
            float c = inb[(size_t)(2 * i + 1) * Tt];
            *(u64*)(xdst + i * 64) = pk2(a, c);
        }
    }
    // stage 0.5||e||^2 for this half
    {
        float* sH = (float*)(smem + HOFF);
#pragma unroll
        for (int i = tid; i < 512; i += TPB) sH[i] = g_half[half * 512 + i];
    }

    u64 best[8];
#pragma unroll
    for (int m = 0; m < 8; m++) best[m] = 0xFFFFFFFFFFFFFFFFull;

    const unsigned char* Xb = smem + XOFF + ml * GSTRIDE;
    const float* sH = (const float*)(smem + HOFF);

    for (int s = 0; s < NSEG; s++) {
        cp_waitn(NSEG - 1 - s);      // segments 0..s complete
        __syncthreads();             // visibility of other threads' copies (fill phase only)

        const unsigned char* Eb = smem + EOFF + s * SEG_BYTES + kl * GSTRIDE;

        u64 acc[8][8];
#pragma unroll
        for (int m = 0; m < 8; m++)
#pragma unroll
            for (int k = 0; k < 8; k++) acc[m][k] = 0;

#pragma unroll 4
        for (int i = 0; i < 32; i++) {
            ulonglong2 x0 = *(const ulonglong2*)(Xb + i * 64);
            ulonglong2 x1 = *(const ulonglong2*)(Xb + i * 64 + 16);
            ulonglong2 x2 = *(const ulonglong2*)(Xb + i * 64 + 32);
            ulonglong2 x3 = *(const ulonglong2*)(Xb + i * 64 + 48);
            ulonglong2 e0 = *(const ulonglong2*)(Eb + i * 64);
            ulonglong2 e1 = *(const ulonglong2*)(Eb + i * 64 + 16);
            ulonglong2 e2 = *(const ulonglong2*)(Eb + i * 64 + 32);
            ulonglong2 e3 = *(const ulonglong2*)(Eb + i * 64 + 48);
            u64 xv[8] = {x0.x, x0.y, x1.x, x1.y, x2.x, x2.y, x3.x, x3.y};
            u64 ev[8] = {e0.x, e0.y, e1.x, e1.y, e2.x, e2.y, e3.x, e3.y};
#pragma unroll
            for (int m = 0; m < 8; m++)
#pragma unroll
                for (int k = 0; k < 8; k++)
                    fma2(acc[m][k], xv[m], ev[k]);
        }

        // fold into per-token best keys (global code index)
        const int lbase = s * 64 + kl * 8;           // local within half
        const int cbase = half * 512 + lbase;        // global code index
        float hs[8];
#pragma unroll
        for (int k = 0; k < 8; k++) hs[k] = sH[lbase + k];
#pragma unroll
        for (int m = 0; m < 8; m++) {
#pragma unroll
            for (int k = 0; k < 8; k++) {
                float sc = hs[k] - hsum2(acc[m][k]);
                u64 key = ((u64)mono(sc) << 32) | (uint32_t)(cbase + k);
                if (key < best[m]) best[m] = key;
            }
        }
        // NO trailing barrier: segment buffers are never reused
    }

    // reduce across the 8 code-lanes (same token rows)
#pragma unroll
    for (int off = 1; off < 8; off <<= 1) {
#pragma unroll
        for (int m = 0; m < 8; m++) {
            u64 o = __shfl_xor_sync(0xffffffffu, best[m], off);
            if (o < best[m]) best[m] = o;
        }
    }
    if (kl == 0) {
        const size_t tok0 = (size_t)tile * TOK + ml * 8;
#pragma unroll
        for (int m = 0; m < 8; m++)
            g_keys[(size_t)half * Nn + tok0 + m] = best[m];
    }
}

// ---- kernel B: merge halves, gather code vector, scatter outputs ----
__global__ __launch_bounds__(256)
void vq_merge(const float* __restrict__ cb, float* __restrict__ out,
              float* __restrict__ out_idx) {
    const int tok = blockIdx.x * 256 + threadIdx.x;      // 0..Nn-1
    u64 k0 = g_keys[tok];
    u64 k1 = g_keys[(size_t)Nn + tok];
    const int bidx = (int)((k0 < k1 ? k0 : k1) & 0xFFFFFFFFu);

    const int b = tok >> 13;            // /8192
    const int t = tok & (Tt - 1);
    float* ob = out + (size_t)b * Dd * Tt + t;
    const float4* cv = (const float4*)(cb + (size_t)bidx * Dd);
#pragma unroll
    for (int i = 0; i < Dd / 4; i++) {
        float4 v = cv[i];
        ob[(size_t)(4 * i + 0) * Tt] = v.x;
        ob[(size_t)(4 * i + 1) * Tt] = v.y;
        ob[(size_t)(4 * i + 2) * Tt] = v.z;
        ob[(size_t)(4 * i + 3) * Tt] = v.w;
    }
    if (out_idx != nullptr) out_idx[tok] = (float)bidx;
}

extern "C" void kernel_launch(void* const* d_in, const int* in_sizes, int n_in,
                              void* d_out, int out_size) {
    const float* input = (const float*)d_in[0];   // (16, 64, 8192) fp32
    const float* cb    = (const float*)d_in[1];   // (1024, 64) fp32
    float* out = (float*)d_out;

    float* out_idx = nullptr;
    if (out_size >= (int)((long)Nn * Dd + Nn)) out_idx = out + (long)Nn * Dd;

    cudaFuncSetAttribute(vq_half, cudaFuncAttributeMaxDynamicSharedMemorySize, SMEM_BYTES);

    vq_pre<<<(Kk + 127) / 128, 128>>>(cb);
    dim3 gridA(Nn / TOK, 2);
    vq_half<<<gridA, TPB, SMEM_BYTES>>>(input);
    vq_merge<<<Nn / 256, 256>>>(cb, out, out_idx);
}

// round 17
// speedup vs baseline: 1.0862x; 1.0862x over previous
#include <cuda_runtime.h>
#include <cstdint>

// VectorQuantizer: input (16, 64, 8192) fp32, codebook (1024, 64) fp32
// score(n,k) = 0.5*||e_k||^2 - x_n . e_k   (argmin-equivalent to ||x - e||^2)
//
// R17 = R8 champion (8x8 fp32x2 register-tile GEMM, mono-key argmin,
// 2 CTAs/SM) with CK doubled to 128: chunk transitions (syncthreads +
// cp_wait + acc-init + epilogue exposure) halve from 16 to 8.

#define Dd 64
#define Kk 1024
#define Bb 16
#define Tt 8192
#define Nn (Bb * Tt)             // 131072 tokens
#define TPB 128
#define TOK_PER_CTA 128
#define CK 128                   // codes per chunk (doubled vs R8)
#define NCHUNK (Kk / CK)         // 8

#define GSTRIDE 2064             // 8-entry group: 32 dpairs*64B + 16B pad (== 16 mod 128)
#define CHUNK_BYTES (16 * GSTRIDE)       // 33024 (128 codes = 16 groups)
#define XOFF 0                   // X image: 16 groups
#define XBYTES (16 * GSTRIDE)            // 33024
#define EOFF0 XBYTES
#define EOFF1 (EOFF0 + CHUNK_BYTES)      // 66048
#define HOFF  (EOFF1 + CHUNK_BYTES)      // 99072
#define IOFF  (HOFF + 4096)              // 103168
#define SMEM_BYTES (IOFF + 512)          // 103680  -> 2 CTAs/SM

__device__ float g_half[Kk];
__device__ __align__(16) unsigned char g_cbT[NCHUNK * CHUNK_BYTES];

typedef unsigned long long u64;

// ---- packed f32x2 helpers ----
__device__ __forceinline__ u64 pk2(float a, float b) {
    u64 r; asm("mov.b64 %0, {%1, %2};" : "=l"(r) : "f"(a), "f"(b)); return r;
}
__device__ __forceinline__ void fma2(u64& acc, u64 a, u64 b) {
    asm("fma.rn.f32x2 %0, %1, %2, %0;" : "+l"(acc) : "l"(a), "l"(b));
}
__device__ __forceinline__ float hsum2(u64 v) {
    float lo, hi; asm("mov.b64 {%0, %1}, %2;" : "=f"(lo), "=f"(hi) : "l"(v));
    return lo + hi;
}
// order-preserving float -> u32 (exact, bijective)
__device__ __forceinline__ uint32_t mono(float f) {
    uint32_t b = __float_as_uint(f);
    return b ^ (uint32_t)(((int32_t)b >> 31) | 0x80000000);
}

// ---- cp.async helpers ----
__device__ __forceinline__ void cp16(uint32_t dst, const void* src) {
    uint64_t g = __cvta_generic_to_global(src);
    asm volatile("cp.async.cg.shared.global [%0], [%1], 16;" :: "r"(dst), "l"(g) : "memory");
}
__device__ __forceinline__ void cp_commit() { asm volatile("cp.async.commit_group;" ::: "memory"); }
template <int N>
__device__ __forceinline__ void cp_wait() { asm volatile("cp.async.wait_group %0;" :: "n"(N) : "memory"); }

__device__ __forceinline__ uint32_t s2u(const void* p) {
    uint32_t a;
    asm("{ .reg .u64 t; cvta.to.shared.u64 t, %1; cvt.u32.u64 %0, t; }" : "=r"(a) : "l"(p));
    return a;
}

// ---- prologue: 0.5||e||^2 + padded transposed codebook image ----
// chunk c = k>>7, group g = (k>>3)&15, entry j = k&7
__global__ void vq_pre(const float* __restrict__ cb) {
    int k = blockIdx.x * blockDim.x + threadIdx.x;
    if (k >= Kk) return;
    const float* row = cb + k * Dd;
    float s = 0.f;
    unsigned char* dst = g_cbT + (k >> 7) * CHUNK_BYTES + ((k >> 3) & 15) * GSTRIDE + (k & 7) * 8;
#pragma unroll
    for (int i = 0; i < 32; i++) {
        float a = row[2 * i], b = row[2 * i + 1];
        s += a * a + b * b;
        *(u64*)(dst + i * 64) = pk2(a, b);
    }
    g_half[k] = 0.5f * s;
}

__global__ __launch_bounds__(TPB, 2)
void vq_main(const float* __restrict__ input, const float* __restrict__ cb,
             float* __restrict__ out, float* __restrict__ out_idx) {
    extern __shared__ __align__(16) unsigned char smem[];
    const uint32_t sb = s2u(smem);

    const int tid = threadIdx.x;
    const int kl  = tid & 7;        // code-group lane (8 codes per group set)
    const int ml  = tid >> 3;       // token-group (8 tokens)
    const int tile = blockIdx.x;    // 0..1023
    const int b    = tile >> 6;
    const int tb   = (tile & 63) * TOK_PER_CTA;

    // prefetch codebook chunk 0 (2064 16B-slots)
#pragma unroll
    for (int s = 0; s < 17; s++) {
        int idx = tid + s * TPB;
        if (idx < CHUNK_BYTES / 16)
            cp16(sb + EOFF0 + idx * 16, g_cbT + idx * 16);
    }
    cp_commit();

    // stage X tile: token t = tb + tid, packed pairs along D
    {
        const float* inb = input + (size_t)b * Dd * Tt + tb + tid;
        unsigned char* xdst = smem + XOFF + (tid >> 3) * GSTRIDE + (tid & 7) * 8;
#pragma unroll 8
        for (int i = 0; i < 32; i++) {
            float a = inb[(size_t)(2 * i) * Tt];
            float c = inb[(size_t)(2 * i + 1) * Tt];
            *(u64*)(xdst + i * 64) = pk2(a, c);
        }
    }
    {
        float* sH = (float*)(smem + HOFF);
#pragma unroll
        for (int i = tid; i < Kk; i += TPB) sH[i] = g_half[i];
    }

    u64 best[8];
#pragma unroll
    for (int m = 0; m < 8; m++) best[m] = 0xFFFFFFFFFFFFFFFFull;

    const unsigned char* Xb = smem + XOFF + ml * GSTRIDE;
    const float* sH = (const float*)(smem + HOFF);

    for (int c = 0; c < NCHUNK; c++) {
        const int st = c & 1;
        if (c + 1 < NCHUNK) {
            const uint32_t nxt = sb + (st ? EOFF0 : EOFF1);
            const unsigned char* src = g_cbT + (size_t)(c + 1) * CHUNK_BYTES;
#pragma unroll
            for (int s = 0; s < 17; s++) {
                int idx = tid + s * TPB;
                if (idx < CHUNK_BYTES / 16)
                    cp16(nxt + idx * 16, src + idx * 16);
            }
            cp_commit();
            cp_wait<1>();
        } else {
            cp_wait<0>();
        }
        __syncthreads();

        const unsigned char* EbC = smem + (st ? EOFF1 : EOFF0);

        // two 64-code passes over this chunk (group sets 0-7 and 8-15)
#pragma unroll 1
        for (int half = 0; half < 2; half++) {
            const unsigned char* Eb = EbC + (half * 8 + kl) * GSTRIDE;

            u64 acc[8][8];
#pragma unroll
            for (int m = 0; m < 8; m++)
#pragma unroll
                for (int k = 0; k < 8; k++) acc[m][k] = 0;

#pragma unroll 4
            for (int i = 0; i < 32; i++) {
                ulonglong2 x0 = *(const ulonglong2*)(Xb + i * 64);
                ulonglong2 x1 = *(const ulonglong2*)(Xb + i * 64 + 16);
                ulonglong2 x2 = *(const ulonglong2*)(Xb + i * 64 + 32);
                ulonglong2 x3 = *(const ulonglong2*)(Xb + i * 64 + 48);
                ulonglong2 e0 = *(const ulonglong2*)(Eb + i * 64);
                ulonglong2 e1 = *(const ulonglong2*)(Eb + i * 64 + 16);
                ulonglong2 e2 = *(const ulonglong2*)(Eb + i * 64 + 32);
                ulonglong2 e3 = *(const ulonglong2*)(Eb + i * 64 + 48);
                u64 xv[8] = {x0.x, x0.y, x1.x, x1.y, x2.x, x2.y, x3.x, x3.y};
                u64 ev[8] = {e0.x, e0.y, e1.x, e1.y, e2.x, e2.y, e3.x, e3.y};
#pragma unroll
                for (int m = 0; m < 8; m++)
#pragma unroll
                    for (int k = 0; k < 8; k++)
                        fma2(acc[m][k], xv[m], ev[k]);
            }

            // fold into per-token best keys
            const int cbase = c * CK + half * 64 + kl * 8;
            float hs[8];
#pragma unroll
            for (int k = 0; k < 8; k++) hs[k] = sH[cbase + k];
#pragma unroll
            for (int m = 0; m < 8; m++) {
#pragma unroll
                for (int k = 0; k < 8; k++) {
                    float s = hs[k] - hsum2(acc[m][k]);
                    u64 key = ((u64)mono(s) << 32) | (uint32_t)(cbase + k);
                    if (key < best[m]) best[m] = key;
                }
            }
        }
        __syncthreads();   // protect E buffer before next prefetch lands
    }

    // reduce across the 8 code-lanes (same token rows)
#pragma unroll
    for (int off = 1; off < 8; off <<= 1) {
#pragma unroll
        for (int m = 0; m < 8; m++) {
            u64 o = __shfl_xor_sync(0xffffffffu, best[m], off);
            if (o < best[m]) best[m] = o;
        }
    }
    int* sIdx = (int*)(smem + IOFF);
    if (kl == 0) {
#pragma unroll
        for (int m = 0; m < 8; m++) sIdx[ml * 8 + m] = (int)(best[m] & 0xFFFFFFFFu);
    }
    __syncthreads();

    // scatter: thread tid owns token tb + tid
    {
        const int bidx = sIdx[tid];
        const int t = tb + tid;
        float* ob = out + (size_t)b * Dd * Tt + t;
        const float4* cv = (const float4*)(cb + (size_t)bidx * Dd);
#pragma unroll
        for (int i = 0; i < Dd / 4; i++) {
            float4 v = cv[i];
            ob[(size_t)(4 * i + 0) * Tt] = v.x;
            ob[(size_t)(4 * i + 1) * Tt] = v.y;
            ob[(size_t)(4 * i + 2) * Tt] = v.z;
            ob[(size_t)(4 * i + 3) * Tt] = v.w;
        }
        if (out_idx != nullptr) out_idx[(size_t)b * Tt + t] = (float)bidx;
    }
}

extern "C" void kernel_launch(void* const* d_in, const int* in_sizes, int n_in,
                              void* d_out, int out_size) {
    const float* input = (const float*)d_in[0];   // (16, 64, 8192) fp32
    const float* cb    = (const float*)d_in[1];   // (1024, 64) fp32
    float* out = (float*)d_out;

    float* out_idx = nullptr;
    if (out_size >= (int)((long)Nn * Dd + Nn)) out_idx = out + (long)Nn * Dd;

    cudaFuncSetAttribute(vq_main, cudaFuncAttributeMaxDynamicSharedMemorySize, SMEM_BYTES);

    vq_pre<<<(Kk + 127) / 128, 128>>>(cb);
    vq_main<<<Nn / TOK_PER_CTA, TPB, SMEM_BYTES>>>(input, cb, out, out_idx);
}